// round 7
// baseline (speedup 1.0000x reference)
#include <cuda_runtime.h>

// Pool_26517128085982: 2x2 mean pool, stride 2, x:(16,64,512,512) f32 -> (16,64,256,256) f32
// Converged HBM-streaming kernel (~7.25 TB/s, 90.6% of spec; compulsory 1.342 GB traffic).
// R7: persistent grid-stride form (1184 CTAs = 8/SM) to eliminate ~33 waves of CTA
// launch/drain churn; 2 outputs per loop iteration (MLP=8); default caching (R6 showed
// .cs hints cost ~1.5% DRAM efficiency). Second element guarded for the final partial pass.

static constexpr int W_IN    = 512;
static constexpr int W_OUT   = 256;
static constexpr int H_OUT   = 256;
static constexpr int ROW4_IN  = W_IN / 4;          // 128 float4 per input row
static constexpr int ROW4_OUT = W_OUT / 4;         // 64  float4 per output row
static constexpr int IMG4_IN  = W_IN * W_IN / 4;   // 65536 float4 per input image

__device__ __forceinline__ float4 pool_one(const float4* __restrict__ in,
                                           int idx, const float4& k)
{
    int oc4 = idx & (ROW4_OUT - 1);
    int oh  = (idx >> 6) & (H_OUT - 1);
    int img = idx >> 14;
    int base = img * IMG4_IN + (oh << 1) * ROW4_IN + (oc4 << 1);

    float4 a0 = in[base];
    float4 a1 = in[base + 1];
    float4 b0 = in[base + ROW4_IN];
    float4 b1 = in[base + ROW4_IN + 1];

    float4 o;
    o.x = k.x * a0.x + k.y * a0.y + k.z * b0.x + k.w * b0.y;
    o.y = k.x * a0.z + k.y * a0.w + k.z * b0.z + k.w * b0.w;
    o.z = k.x * a1.x + k.y * a1.y + k.z * b1.x + k.w * b1.y;
    o.w = k.x * a1.z + k.y * a1.w + k.z * b1.z + k.w * b1.w;
    return o;
}

__global__ __launch_bounds__(256) void Pool_26517128085982_kernel(
    const float4* __restrict__ in,
    const float*  __restrict__ kern,   // 4 floats: k00 k01 k10 k11
    float4* __restrict__ out,
    int n_out4)
{
    const float4 k = *reinterpret_cast<const float4*>(kern);

    const int stride = gridDim.x * blockDim.x;     // 303,104 threads
    int idx = blockIdx.x * blockDim.x + threadIdx.x;

    #pragma unroll 1
    for (; idx < n_out4; idx += 2 * stride) {
        int idx1 = idx + stride;

        // First element always valid. Compute both (loads front-batched by ptxas
        // within the predicated region), guard the second.
        float4 oA = pool_one(in, idx, k);
        if (idx1 < n_out4) {
            float4 oB = pool_one(in, idx1, k);
            out[idx]  = oA;
            out[idx1] = oB;
        } else {
            out[idx] = oA;
        }
    }
}

extern "C" void kernel_launch(void* const* d_in, const int* in_sizes, int n_in,
                              void* d_out, int out_size)
{
    const float4* x    = (const float4*)d_in[0];
    const float*  kern = (const float*)d_in[1];
    float4*       out  = (float4*)d_out;

    int n_out4 = out_size / 4;           // 16,777,216 float4
    int blocks = 148 * 8;                // 1184 persistent CTAs (8/SM)
    Pool_26517128085982_kernel<<<blocks, 256>>>(x, kern, out, n_out4);
}

// round 8
// speedup vs baseline: 1.0635x; 1.0635x over previous
#include <cuda_runtime.h>

// Pool_26517128085982: 2x2 mean pool, stride 2, x:(16,64,512,512) f32 -> (16,64,256,256) f32
// Converged HBM-streaming kernel. History:
//   R3  flat MLP=4 default-cache:        186.59us, DRAM 91.2%
//   R5  flat MLP=8 .cs hints:            186.75us, DRAM 89.6%  (.cs hurt L2->DRAM efficiency)
//   R6  flat MLP=8 default-cache:        186.56us, DRAM 91.5%  (best)
//   R7  persistent grid-stride:          198.75us, DRAM 85.9%  (loop bubbles starve LDG stream)
// R8: R6 structure + __ldcg input loads (bypass L1 — zero reuse, skip L1 fill; L2 policy
// unchanged, unlike the harmful .cs). Flat one-shot grid, 2 float4 outputs/thread split
// by n/2 so every warp transaction stays fully contiguous.

static constexpr int W_IN    = 512;
static constexpr int W_OUT   = 256;
static constexpr int H_OUT   = 256;
static constexpr int ROW4_IN  = W_IN / 4;          // 128 float4 per input row
static constexpr int ROW4_OUT = W_OUT / 4;         // 64  float4 per output row
static constexpr int IMG4_IN  = W_IN * W_IN / 4;   // 65536 float4 per input image

__device__ __forceinline__ float4 pool4(const float4& a0, const float4& a1,
                                        const float4& b0, const float4& b1,
                                        const float4& k)
{
    float4 o;
    o.x = k.x * a0.x + k.y * a0.y + k.z * b0.x + k.w * b0.y;
    o.y = k.x * a0.z + k.y * a0.w + k.z * b0.z + k.w * b0.w;
    o.z = k.x * a1.x + k.y * a1.y + k.z * b1.x + k.w * b1.y;
    o.w = k.x * a1.z + k.y * a1.w + k.z * b1.z + k.w * b1.w;
    return o;
}

__global__ __launch_bounds__(256) void Pool_26517128085982_kernel(
    const float4* __restrict__ in,
    const float*  __restrict__ kern,   // 4 floats: k00 k01 k10 k11
    float4* __restrict__ out,
    int half_n4)                       // n_out4 / 2
{
    int idx0 = blockIdx.x * blockDim.x + threadIdx.x;
    if (idx0 >= half_n4) return;
    int idx1 = idx0 + half_n4;

    // idx -> (img, oh, oc4): 64 float4 per out row, 256 rows per image
    int oc4a = idx0 & (ROW4_OUT - 1);
    int oha  = (idx0 >> 6) & (H_OUT - 1);
    int imga = idx0 >> 14;
    int basea = imga * IMG4_IN + (oha << 1) * ROW4_IN + (oc4a << 1);

    int oc4b = idx1 & (ROW4_OUT - 1);
    int ohb  = (idx1 >> 6) & (H_OUT - 1);
    int imgb = idx1 >> 14;
    int baseb = imgb * IMG4_IN + (ohb << 1) * ROW4_IN + (oc4b << 1);

    // 8 independent LDG.128.CG (MLP=8), front-batched, L1-bypass / L2 evict-normal
    float4 a0 = __ldcg(in + basea);
    float4 a1 = __ldcg(in + basea + 1);
    float4 b0 = __ldcg(in + basea + ROW4_IN);
    float4 b1 = __ldcg(in + basea + ROW4_IN + 1);
    float4 c0 = __ldcg(in + baseb);
    float4 c1 = __ldcg(in + baseb + 1);
    float4 d0 = __ldcg(in + baseb + ROW4_IN);
    float4 d1 = __ldcg(in + baseb + ROW4_IN + 1);

    // kernel weights: broadcast load, L1-hit after first warp
    float4 k = *reinterpret_cast<const float4*>(kern);

    out[idx0] = pool4(a0, a1, b0, b1, k);
    out[idx1] = pool4(c0, c1, d0, d1, k);
}

extern "C" void kernel_launch(void* const* d_in, const int* in_sizes, int n_in,
                              void* d_out, int out_size)
{
    const float4* x    = (const float4*)d_in[0];
    const float*  kern = (const float*)d_in[1];
    float4*       out  = (float4*)d_out;

    int n_out4  = out_size / 4;          // 16,777,216 float4
    int half_n4 = n_out4 / 2;            // 8,388,608 threads
    int blocks  = (half_n4 + 255) / 256; // 32,768 blocks
    Pool_26517128085982_kernel<<<blocks, 256>>>(x, kern, out, half_n4);
}

// round 9
// speedup vs baseline: 1.0650x; 1.0014x over previous
#include <cuda_runtime.h>

// Pool_26517128085982: 2x2 mean pool, stride 2, x:(16,64,512,512) f32 -> (16,64,256,256) f32
// Converged HBM-streaming kernel at the DRAM roofline. History:
//   R3  flat MLP=4 default:       186.59us, DRAM 91.2%
//   R5  flat MLP=8 .cs:           186.75us, DRAM 89.6%  (.cs hurts L2->DRAM scheduling)
//   R6  flat MLP=8 default:       186.56us, DRAM 91.5%  (best)
//   R7  persistent grid-stride:   198.75us, DRAM 85.9%  (loop bubbles starve LDG stream)
//   R8  flat MLP=8 .cg:           186.88us, DRAM 91.4%  (L1 bypass neutral)
// R9: final axis — block=512 (16384 CTAs; coarser, row-aligned work quanta). Body is
// R6's proven-best: flat one-shot grid, default caching, 2 float4 outputs/thread split
// by n/2 so every warp transaction is fully contiguous, MLP=8.
// Traffic is compulsory (1.342 GB); ~91.5% DRAM cycles-active is the practical ceiling.

static constexpr int W_IN    = 512;
static constexpr int W_OUT   = 256;
static constexpr int H_OUT   = 256;
static constexpr int ROW4_IN  = W_IN / 4;          // 128 float4 per input row
static constexpr int ROW4_OUT = W_OUT / 4;         // 64  float4 per output row
static constexpr int IMG4_IN  = W_IN * W_IN / 4;   // 65536 float4 per input image

__device__ __forceinline__ float4 pool4(const float4& a0, const float4& a1,
                                        const float4& b0, const float4& b1,
                                        const float4& k)
{
    float4 o;
    o.x = k.x * a0.x + k.y * a0.y + k.z * b0.x + k.w * b0.y;
    o.y = k.x * a0.z + k.y * a0.w + k.z * b0.z + k.w * b0.w;
    o.z = k.x * a1.x + k.y * a1.y + k.z * b1.x + k.w * b1.y;
    o.w = k.x * a1.z + k.y * a1.w + k.z * b1.z + k.w * b1.w;
    return o;
}

__global__ __launch_bounds__(512) void Pool_26517128085982_kernel(
    const float4* __restrict__ in,
    const float*  __restrict__ kern,   // 4 floats: k00 k01 k10 k11
    float4* __restrict__ out,
    int half_n4)                       // n_out4 / 2
{
    int idx0 = blockIdx.x * blockDim.x + threadIdx.x;
    if (idx0 >= half_n4) return;
    int idx1 = idx0 + half_n4;

    // idx -> (img, oh, oc4): 64 float4 per out row, 256 rows per image
    int oc4a = idx0 & (ROW4_OUT - 1);
    int oha  = (idx0 >> 6) & (H_OUT - 1);
    int imga = idx0 >> 14;
    int basea = imga * IMG4_IN + (oha << 1) * ROW4_IN + (oc4a << 1);

    int oc4b = idx1 & (ROW4_OUT - 1);
    int ohb  = (idx1 >> 6) & (H_OUT - 1);
    int imgb = idx1 >> 14;
    int baseb = imgb * IMG4_IN + (ohb << 1) * ROW4_IN + (oc4b << 1);

    // 8 independent LDG.128 (MLP=8), front-batched, default caching
    float4 a0 = in[basea];
    float4 a1 = in[basea + 1];
    float4 b0 = in[basea + ROW4_IN];
    float4 b1 = in[basea + ROW4_IN + 1];
    float4 c0 = in[baseb];
    float4 c1 = in[baseb + 1];
    float4 d0 = in[baseb + ROW4_IN];
    float4 d1 = in[baseb + ROW4_IN + 1];

    // kernel weights: broadcast load, L1-hit after first warp
    float4 k = *reinterpret_cast<const float4*>(kern);

    out[idx0] = pool4(a0, a1, b0, b1, k);
    out[idx1] = pool4(c0, c1, d0, d1, k);
}

extern "C" void kernel_launch(void* const* d_in, const int* in_sizes, int n_in,
                              void* d_out, int out_size)
{
    const float4* x    = (const float4*)d_in[0];
    const float*  kern = (const float*)d_in[1];
    float4*       out  = (float4*)d_out;

    int n_out4  = out_size / 4;          // 16,777,216 float4
    int half_n4 = n_out4 / 2;            // 8,388,608 threads
    int blocks  = (half_n4 + 511) / 512; // 16,384 blocks
    Pool_26517128085982_kernel<<<blocks, 512>>>(x, kern, out, half_n4);
}